// round 2
// baseline (speedup 1.0000x reference)
#include <cuda_runtime.h>
#include <cuda_bf16.h>
#include <cstdint>

// ---------------------------------------------------------------------------
// DependencyParsingNetwork: emb-gather + 2-layer BiLSTM (H=50) + pairwise tanh
// Strategy:
//   1) build x0 = [emb[token] | pos]            (parallel)
//   2) pre0 = x0 @ w_ih_l0^T + b                (GEMM, parallel over time)
//   3) layer-0 recurrence (fwd & bwd CTAs)      (sequential, latency-critical)
//   4) pre1 = h0 @ w_ih_l1^T + b                (GEMM)
//   5) layer-1 recurrence
//   6) s_i, s_j dots; epilogue tanh(s_i+s_j+b) masked to strict upper triangle
// ---------------------------------------------------------------------------

#define NMAX 8192
#define HH   50

__device__ float g_x0[NMAX * 352];          // [n][352] (K=350 padded)
__device__ float g_pre0[2 * NMAX * 200];    // [dir][n][200]
__device__ float g_pre1[2 * NMAX * 200];
__device__ float g_h0[NMAX * 100];          // [n][fwd 0:50 | bwd 50:100]
__device__ float g_h1[NMAX * 100];
__device__ float g_si[NMAX];
__device__ float g_sj[NMAX];

// ---------------- packed f32x2 helpers (Blackwell) -------------------------
__device__ __forceinline__ unsigned long long pack2(float x, float y) {
    unsigned long long r;
    asm("mov.b64 %0, {%1,%2};" : "=l"(r) : "f"(x), "f"(y));
    return r;
}
__device__ __forceinline__ float2 unpack2(unsigned long long v) {
    float2 r;
    asm("mov.b64 {%0,%1}, %2;" : "=f"(r.x), "=f"(r.y) : "l"(v));
    return r;
}
__device__ __forceinline__ unsigned long long fma2(unsigned long long a,
                                                   unsigned long long b,
                                                   unsigned long long c) {
    unsigned long long d;
    asm("fma.rn.f32x2 %0, %1, %2, %3;" : "=l"(d) : "l"(a), "l"(b), "l"(c));
    return d;
}

__device__ __forceinline__ float tanh_acc(float x) {
    // tanh(x) = 2/(1+e^{-2x}) - 1, EX2+RCP based (accurate to ~1e-7 rel)
    float e = __expf(-2.0f * x);
    return __fdividef(2.0f, 1.0f + e) - 1.0f;
}

// ---------------- 1) build x0 ----------------------------------------------
__global__ void build_x0_kernel(const int* __restrict__ tok,
                                const float* __restrict__ pos,
                                const float* __restrict__ emb,
                                float* __restrict__ x0, int n) {
    int t = blockIdx.x;
    int tk = tok[t];
    for (int k = threadIdx.x; k < 352; k += blockDim.x) {
        float v;
        if (k < 300)      v = emb[(size_t)tk * 300 + k];
        else if (k < 350) v = pos[t * 50 + (k - 300)];
        else              v = 0.0f;
        x0[(size_t)t * 352 + k] = v;
    }
}

// ---------------- 2) GEMM: C[M,N] = A[M,K] * B[N,K]^T + bias ---------------
__global__ void __launch_bounds__(256)
gemm_bias_kernel(const float* __restrict__ A, int lda,
                 const float* __restrict__ B, int ldb,
                 const float* __restrict__ bias,
                 float* __restrict__ C, int ldc,
                 int M, int N, int K) {
    const int BM = 64, BN = 64, BK = 16;
    __shared__ __align__(16) float As[BK][BM + 4];
    __shared__ __align__(16) float Bs[BK][BN + 4];
    int tid = threadIdx.x;
    int bm = blockIdx.x * BM, bn = blockIdx.y * BN;
    int tx = tid & 15, ty = tid >> 4;

    float acc[4][4];
#pragma unroll
    for (int i = 0; i < 4; i++)
#pragma unroll
        for (int j = 0; j < 4; j++) acc[i][j] = 0.0f;

    for (int k0 = 0; k0 < K; k0 += BK) {
#pragma unroll
        for (int i = 0; i < 4; i++) {
            int idx = tid + i * 256;           // 0..1023
            int kk = idx & 15, m = idx >> 4;   // kk fast -> coalesced A reads
            int gm = bm + m, gk = k0 + kk;
            float v = 0.0f;
            if (gm < M && gk < K) v = A[(size_t)gm * lda + gk];
            As[kk][m] = v;
        }
#pragma unroll
        for (int i = 0; i < 4; i++) {
            int idx = tid + i * 256;
            int kk = idx & 15, nn = idx >> 4;
            int gn = bn + nn, gk = k0 + kk;
            float v = 0.0f;
            if (gn < N && gk < K) v = B[(size_t)gn * ldb + gk];
            Bs[kk][nn] = v;
        }
        __syncthreads();
#pragma unroll
        for (int kk = 0; kk < BK; kk++) {
            float4 a4 = *reinterpret_cast<const float4*>(&As[kk][ty * 4]);
            float4 b4 = *reinterpret_cast<const float4*>(&Bs[kk][tx * 4]);
            float a[4] = {a4.x, a4.y, a4.z, a4.w};
            float b[4] = {b4.x, b4.y, b4.z, b4.w};
#pragma unroll
            for (int i = 0; i < 4; i++)
#pragma unroll
                for (int j = 0; j < 4; j++) acc[i][j] += a[i] * b[j];
        }
        __syncthreads();
    }
#pragma unroll
    for (int i = 0; i < 4; i++) {
        int gm = bm + ty * 4 + i;
        if (gm >= M) continue;
#pragma unroll
        for (int j = 0; j < 4; j++) {
            int gn = bn + tx * 4 + j;
            if (gn < N) C[(size_t)gm * ldc + gn] = acc[i][j] + bias[gn];
        }
    }
}

// ---------------- 3/5) persistent recurrence, one CTA per direction --------
// Thread t: j = t>>2 (output index), g = t&3 (gate: 0=i,1=f,2=g,3=o),
// gate row r = g*50 + j. Gates of output j live in quad lanes 4j..4j+3 ->
// exchanged with 3 shfl.bfly, lane g==0 owns c_j and writes h_j.
__global__ void __launch_bounds__(256, 1)
lstm_layer_kernel(const float* __restrict__ pre,   // [2][n][200]
                  const float* __restrict__ whh_f, // [200][50]
                  const float* __restrict__ whh_b,
                  float* __restrict__ hout,        // [n][100]
                  int n) {
    const int dir = blockIdx.x;                    // 0 fwd, 1 bwd
    const float* __restrict__ preD = pre + (size_t)dir * n * 200;
    const float* __restrict__ whh = dir ? whh_b : whh_f;

    int t = threadIdx.x;
    int j = t >> 2, g = t & 3;
    bool active = (j < HH);
    int r = g * HH + j;

    // persistent weight row in registers (25 packed pairs)
    unsigned long long w[25];
#pragma unroll
    for (int k = 0; k < 25; k++) {
        if (active)
            w[k] = *reinterpret_cast<const unsigned long long*>(whh + r * HH + 2 * k);
        else
            w[k] = 0ull;
    }

    __shared__ __align__(16) float hsh[2][56];
    if (t < 56) { hsh[0][t] = 0.0f; hsh[1][t] = 0.0f; }
    float c = 0.0f;

    // prefetch pipeline (2 deep)
    float pa0 = 0.0f, pa1 = 0.0f;
    int t0 = dir ? (n - 1) : 0;
    int t1 = dir ? (n - 2) : 1;
    if (active) pa0 = preD[(size_t)t0 * 200 + r];
    if (active && n > 1) pa1 = preD[(size_t)t1 * 200 + r];
    __syncthreads();

    for (int s = 0; s < n; s++) {
        int tt = dir ? (n - 1 - s) : s;
        float pa = pa0;
        pa0 = pa1;
        if (active && s + 2 < n) {
            int tnn = dir ? (n - 3 - s) : (s + 2);
            pa1 = preD[(size_t)tnn * 200 + r];
        }

        // ---- matvec: acc += W_hh[r,:] . h  (packed f32x2) ----
        const float* hb = hsh[s & 1];
        unsigned long long acc0 = pack2(pa, 0.0f);
        unsigned long long acc1 = pack2(0.0f, 0.0f);
#pragma unroll
        for (int i = 0; i < 12; i++) {
            float4 hv = *reinterpret_cast<const float4*>(hb + 4 * i);
            acc0 = fma2(w[2 * i],     pack2(hv.x, hv.y), acc0);
            acc1 = fma2(w[2 * i + 1], pack2(hv.z, hv.w), acc1);
        }
        {
            float2 ht = *reinterpret_cast<const float2*>(hb + 48);
            acc0 = fma2(w[24], pack2(ht.x, ht.y), acc0);
        }
        float2 u0 = unpack2(acc0), u1 = unpack2(acc1);
        float v = (u0.x + u0.y) + (u1.x + u1.y);

        // ---- activation: sigma for i/f/o, tanh for g (one EX2+RCP) ----
        float xx = (g == 2) ? (2.0f * v) : v;
        float e = __expf(-xx);
        float sg = __fdividef(1.0f, 1.0f + e);
        float y = (g == 2) ? (2.0f * sg - 1.0f) : sg;

        // ---- quad exchange of the 4 gate activations ----
        float s1 = __shfl_xor_sync(0xFFFFFFFFu, y, 1);
        float s2 = __shfl_xor_sync(0xFFFFFFFFu, y, 2);
        float s3 = __shfl_xor_sync(0xFFFFFFFFu, y, 3);

        if (g == 0 && active) {
            // lane g==0: y=sig(i), s1=sig(f), s2=tanh(g), s3=sig(o)
            c = s1 * c + y * s2;
            float th = tanh_acc(c);
            float h = s3 * th;
            hsh[(s + 1) & 1][j] = h;
            hout[(size_t)tt * 100 + dir * HH + j] = h;
        }
        __syncthreads();
    }
}

// ---------------- 6a) per-token endpoint scores ----------------------------
__global__ void score_vec_kernel(const float* __restrict__ h1,
                                 const float* __restrict__ mlpw,
                                 float* __restrict__ si, float* __restrict__ sj,
                                 int n) {
    int t = blockIdx.x * blockDim.x + threadIdx.x;
    if (t >= n) return;
    const float* x = h1 + (size_t)t * 100;
    float a = 0.0f, b = 0.0f;
#pragma unroll 4
    for (int k = 0; k < 100; k++) {
        float xv = x[k];
        a += xv * __ldg(mlpw + k);
        b += xv * __ldg(mlpw + 100 + k);
    }
    si[t] = a;
    sj[t] = b;
}

// ---------------- 6b) pairwise epilogue ------------------------------------
__global__ void __launch_bounds__(256)
epilogue_kernel(const float* __restrict__ si, const float* __restrict__ sj,
                const float* __restrict__ mb, float* __restrict__ out, int n) {
    int i = blockIdx.y;
    int j4 = blockIdx.x * blockDim.x + threadIdx.x;
    int j0 = j4 * 4;
    if (j0 >= n) return;
    float base = si[i] + mb[0];
    float4 r;
    r.x = (j0 + 0 > i) ? tanh_acc(base + sj[j0 + 0]) : 0.0f;
    r.y = (j0 + 1 > i) ? tanh_acc(base + sj[j0 + 1]) : 0.0f;
    r.z = (j0 + 2 > i) ? tanh_acc(base + sj[j0 + 2]) : 0.0f;
    r.w = (j0 + 3 > i) ? tanh_acc(base + sj[j0 + 3]) : 0.0f;
    *reinterpret_cast<float4*>(out + (size_t)i * n + j0) = r;
}

// ---------------------------------------------------------------------------
extern "C" void kernel_launch(void* const* d_in, const int* in_sizes, int n_in,
                              void* d_out, int out_size) {
    const int*   tok   = (const int*)d_in[0];
    const float* pos   = (const float*)d_in[1];
    const float* emb   = (const float*)d_in[2];
    const float* wih0f = (const float*)d_in[3];
    const float* whh0f = (const float*)d_in[4];
    const float* b0f   = (const float*)d_in[5];
    const float* wih0b = (const float*)d_in[6];
    const float* whh0b = (const float*)d_in[7];
    const float* b0b   = (const float*)d_in[8];
    const float* wih1f = (const float*)d_in[9];
    const float* whh1f = (const float*)d_in[10];
    const float* b1f   = (const float*)d_in[11];
    const float* wih1b = (const float*)d_in[12];
    const float* whh1b = (const float*)d_in[13];
    const float* b1b   = (const float*)d_in[14];
    const float* mlpw  = (const float*)d_in[15];
    const float* mlpb  = (const float*)d_in[16];

    int n = in_sizes[0];
    if (n > NMAX) n = NMAX;

    float *x0, *pre0, *pre1, *h0, *h1, *si, *sj;
    cudaGetSymbolAddress((void**)&x0,   g_x0);
    cudaGetSymbolAddress((void**)&pre0, g_pre0);
    cudaGetSymbolAddress((void**)&pre1, g_pre1);
    cudaGetSymbolAddress((void**)&h0,   g_h0);
    cudaGetSymbolAddress((void**)&h1,   g_h1);
    cudaGetSymbolAddress((void**)&si,   g_si);
    cudaGetSymbolAddress((void**)&sj,   g_sj);

    // 1) x0 = [emb[token] | pos]
    build_x0_kernel<<<n, 128>>>(tok, pos, emb, x0, n);

    // 2) layer-0 input projections
    {
        dim3 grid((n + 63) / 64, (200 + 63) / 64);
        gemm_bias_kernel<<<grid, 256>>>(x0, 352, wih0f, 350, b0f,
                                        pre0, 200, n, 200, 350);
        gemm_bias_kernel<<<grid, 256>>>(x0, 352, wih0b, 350, b0b,
                                        pre0 + (size_t)n * 200, 200, n, 200, 350);
    }

    // 3) layer-0 recurrence (fwd CTA + bwd CTA)
    lstm_layer_kernel<<<2, 256>>>(pre0, whh0f, whh0b, h0, n);

    // 4) layer-1 input projections (input = h0, K=100)
    {
        dim3 grid((n + 63) / 64, (200 + 63) / 64);
        gemm_bias_kernel<<<grid, 256>>>(h0, 100, wih1f, 100, b1f,
                                        pre1, 200, n, 200, 100);
        gemm_bias_kernel<<<grid, 256>>>(h0, 100, wih1b, 100, b1b,
                                        pre1 + (size_t)n * 200, 200, n, 200, 100);
    }

    // 5) layer-1 recurrence
    lstm_layer_kernel<<<2, 256>>>(pre1, whh1f, whh1b, h1, n);

    // 6) endpoint scores + pairwise tanh epilogue
    score_vec_kernel<<<(n + 255) / 256, 256>>>(h1, mlpw, si, sj, n);
    {
        dim3 grid((n / 4 + 255) / 256, n);
        epilogue_kernel<<<grid, 256>>>(si, sj, mlpb, (float*)d_out, n);
    }
}

// round 3
// speedup vs baseline: 1.0568x; 1.0568x over previous
#include <cuda_runtime.h>
#include <cuda_bf16.h>
#include <cstdint>

// ---------------------------------------------------------------------------
// DependencyParsingNetwork: emb-gather + 2-layer BiLSTM (H=50) + pairwise tanh
//   1) build x0 = [emb[token] | pos]
//   2) pre0 = x0 @ w_ih_l0^T + b        (GEMM, parallel over time)
//   3) layer-0 recurrence (fwd & bwd CTAs; latency-critical)
//   4) pre1 = h0 @ w_ih_l1^T + b
//   5) layer-1 recurrence
//   6) s_i/s_j dots; epilogue tanh(s_i+s_j+b) on strict upper triangle
//
// R2 recurrence redesign: 128 threads, thread (j,p): p0 owns gate rows i,g;
// p1 owns f,o. Direct LDS.128->b64 fma2 operands (no packs), 1 warp/SMSP,
// 2 shfl exchange, ex2/rcp-based activations with folded constants.
// ---------------------------------------------------------------------------

#define NMAX 8192
#define HH   50

typedef unsigned long long ull;

__device__ float g_x0[NMAX * 352];
__device__ float g_pre0[2 * NMAX * 200];
__device__ float g_pre1[2 * NMAX * 200];
__device__ float g_h0[NMAX * 100];
__device__ float g_h1[NMAX * 100];
__device__ float g_si[NMAX];
__device__ float g_sj[NMAX];

// ---------------- packed f32x2 / MUFU helpers ------------------------------
__device__ __forceinline__ ull pack2(float x, float y) {
    ull r; asm("mov.b64 %0,{%1,%2};" : "=l"(r) : "f"(x), "f"(y)); return r;
}
__device__ __forceinline__ float2 unpack2(ull v) {
    float2 r; asm("mov.b64 {%0,%1},%2;" : "=f"(r.x), "=f"(r.y) : "l"(v)); return r;
}
__device__ __forceinline__ ull fma2(ull a, ull b, ull c) {
    ull d; asm("fma.rn.f32x2 %0,%1,%2,%3;" : "=l"(d) : "l"(a), "l"(b), "l"(c)); return d;
}
__device__ __forceinline__ ull add2(ull a, ull b) {
    ull d; asm("add.rn.f32x2 %0,%1,%2;" : "=l"(d) : "l"(a), "l"(b)); return d;
}
__device__ __forceinline__ float ex2f(float x) {
    float y; asm("ex2.approx.ftz.f32 %0,%1;" : "=f"(y) : "f"(x)); return y;
}
__device__ __forceinline__ float rcpf(float x) {
    float y; asm("rcp.approx.ftz.f32 %0,%1;" : "=f"(y) : "f"(x)); return y;
}
__device__ __forceinline__ float tanh_acc(float x) {
    float e = ex2f(x * -2.8853900817779268f);      // e^{-2x}
    return fmaf(2.0f, rcpf(1.0f + e), -1.0f);
}

// ---------------- 1) build x0 ----------------------------------------------
__global__ void build_x0_kernel(const int* __restrict__ tok,
                                const float* __restrict__ pos,
                                const float* __restrict__ emb,
                                float* __restrict__ x0, int n) {
    int t = blockIdx.x;
    int tk = tok[t];
    for (int k = threadIdx.x; k < 352; k += blockDim.x) {
        float v;
        if (k < 300)      v = emb[(size_t)tk * 300 + k];
        else if (k < 350) v = pos[t * 50 + (k - 300)];
        else              v = 0.0f;
        x0[(size_t)t * 352 + k] = v;
    }
}

// ---------------- 2) GEMM: C[M,N] = A[M,K] * B[N,K]^T + bias ---------------
__global__ void __launch_bounds__(256)
gemm_bias_kernel(const float* __restrict__ A, int lda,
                 const float* __restrict__ B, int ldb,
                 const float* __restrict__ bias,
                 float* __restrict__ C, int ldc,
                 int M, int N, int K) {
    const int BM = 64, BN = 64, BK = 16;
    __shared__ __align__(16) float As[BK][BM + 4];
    __shared__ __align__(16) float Bs[BK][BN + 4];
    int tid = threadIdx.x;
    int bm = blockIdx.x * BM, bn = blockIdx.y * BN;
    int tx = tid & 15, ty = tid >> 4;

    float acc[4][4];
#pragma unroll
    for (int i = 0; i < 4; i++)
#pragma unroll
        for (int j = 0; j < 4; j++) acc[i][j] = 0.0f;

    for (int k0 = 0; k0 < K; k0 += BK) {
#pragma unroll
        for (int i = 0; i < 4; i++) {
            int idx = tid + i * 256;
            int kk = idx & 15, m = idx >> 4;
            int gm = bm + m, gk = k0 + kk;
            float v = 0.0f;
            if (gm < M && gk < K) v = A[(size_t)gm * lda + gk];
            As[kk][m] = v;
        }
#pragma unroll
        for (int i = 0; i < 4; i++) {
            int idx = tid + i * 256;
            int kk = idx & 15, nn = idx >> 4;
            int gn = bn + nn, gk = k0 + kk;
            float v = 0.0f;
            if (gn < N && gk < K) v = B[(size_t)gn * ldb + gk];
            Bs[kk][nn] = v;
        }
        __syncthreads();
#pragma unroll
        for (int kk = 0; kk < BK; kk++) {
            float4 a4 = *reinterpret_cast<const float4*>(&As[kk][ty * 4]);
            float4 b4 = *reinterpret_cast<const float4*>(&Bs[kk][tx * 4]);
            float a[4] = {a4.x, a4.y, a4.z, a4.w};
            float b[4] = {b4.x, b4.y, b4.z, b4.w};
#pragma unroll
            for (int i = 0; i < 4; i++)
#pragma unroll
                for (int j = 0; j < 4; j++) acc[i][j] += a[i] * b[j];
        }
        __syncthreads();
    }
#pragma unroll
    for (int i = 0; i < 4; i++) {
        int gm = bm + ty * 4 + i;
        if (gm >= M) continue;
#pragma unroll
        for (int j = 0; j < 4; j++) {
            int gn = bn + tx * 4 + j;
            if (gn < N) C[(size_t)gm * ldc + gn] = acc[i][j] + bias[gn];
        }
    }
}

// ---------------- 3/5) recurrence: 128 thr, 2 gate rows per thread ---------
// thread t: j = t>>1 (output), p = t&1. p0: rows i (j), g (100+j);
// p1: rows f (50+j), o (150+j). Exchange sig(f),sig(o) via 1-xor shfl pair.
__global__ void __launch_bounds__(128, 1)
lstm_layer_kernel(const float* __restrict__ pre,   // [2][n][200]
                  const float* __restrict__ whh_f, // [200][50]
                  const float* __restrict__ whh_b,
                  float* __restrict__ hout,        // [n][100]
                  int n) {
    const int dir = blockIdx.x;
    const float* __restrict__ preD = pre + (size_t)dir * n * 200;
    const float* __restrict__ whh = dir ? whh_b : whh_f;

    const int t = threadIdx.x;
    const int j = t >> 1, p = t & 1;
    const bool active = (j < HH);
    const int rA = p * HH + j;     // i (p0) / f (p1)
    const int rB = rA + 100;       // g (p0) / o (p1)

    // persistent weight rows (2 x 25 packed pairs); rows are 8B-aligned
    ull wA[25], wB[25];
#pragma unroll
    for (int k = 0; k < 25; k++) {
        if (active) {
            wA[k] = *reinterpret_cast<const ull*>(whh + rA * HH + 2 * k);
            wB[k] = *reinterpret_cast<const ull*>(whh + rB * HH + 2 * k);
        } else { wA[k] = 0ull; wB[k] = 0ull; }
    }

    __shared__ __align__(16) float hsh[2][56];
    if (t < 56) { hsh[0][t] = 0.0f; hsh[1][t] = 0.0f; }
    float c = 0.0f;

    // prefetch pipeline (2 deep), pointer-increment addressing
    const int stepOff = dir ? -200 : 200;
    const float* pf = preD + (size_t)(dir ? (n - 1) : 0) * 200;
    float a0 = 0.0f, b0 = 0.0f, a1 = 0.0f, b1 = 0.0f;
    if (active) { a0 = pf[rA]; b0 = pf[rB]; }
    const float* pf2 = pf + stepOff;
    if (active && n > 1) { a1 = pf2[rA]; b1 = pf2[rB]; }
    pf2 += stepOff;

    float* ph = hout + (size_t)(dir ? (n - 1) : 0) * 100 + dir * HH + j;
    const int hOff = dir ? -100 : 100;

    // activation constants: p0 rowB is tanh (scale 2), p1 rowB is sigmoid
    const float m2  = (p == 0) ? 2.0f : 1.0f;
    const float off = (p == 0) ? -1.0f : 0.0f;
    const float cB  = -1.4426950408889634f * m2;

    __syncthreads();

    for (int s = 0; s < n; s++) {
        float pa = a0, pb = b0;
        a0 = a1; b0 = b1;
        if (s + 2 < n) {
            if (active) { a1 = pf2[rA]; b1 = pf2[rB]; }
            pf2 += stepOff;
        }

        // ---- two 50-dots with packed f32x2, h loaded as b64 pairs ----
        const float* hb = hsh[s & 1];
        ull accA0 = pack2(pa, 0.0f), accA1 = pack2(0.0f, 0.0f);
        ull accB0 = pack2(pb, 0.0f), accB1 = pack2(0.0f, 0.0f);
#pragma unroll
        for (int i = 0; i < 12; i++) {
            ulonglong2 hv = *reinterpret_cast<const ulonglong2*>(hb + 4 * i);
            accA0 = fma2(wA[2 * i],     hv.x, accA0);
            accA1 = fma2(wA[2 * i + 1], hv.y, accA1);
            accB0 = fma2(wB[2 * i],     hv.x, accB0);
            accB1 = fma2(wB[2 * i + 1], hv.y, accB1);
        }
        {
            ull hl = *reinterpret_cast<const ull*>(hb + 48);
            accA0 = fma2(wA[24], hl, accA0);
            accB0 = fma2(wB[24], hl, accB0);
        }
        float vA, vB;
        { float2 f = unpack2(add2(accA0, accA1)); vA = f.x + f.y; }
        { float2 f = unpack2(add2(accB0, accB1)); vB = f.x + f.y; }

        // ---- activations: yA = sig(vA); yB = p0 ? tanh(vB) : sig(vB) ----
        float yA = rcpf(1.0f + ex2f(vA * -1.4426950408889634f));
        float sB = rcpf(1.0f + ex2f(vB * cB));
        float yB = fmaf(m2, sB, off);

        // ---- pair exchange: p0 gets sig(f), sig(o) from p1 ----
        float fR = __shfl_xor_sync(0xFFFFFFFFu, yA, 1);
        float oR = __shfl_xor_sync(0xFFFFFFFFu, yB, 1);

        if (p == 0 && active) {
            c = fmaf(fR, c, yA * yB);          // f*c + i*g
            float h = oR * tanh_acc(c);
            hsh[(s + 1) & 1][j] = h;
            *ph = h;
        }
        ph += hOff;
        __syncthreads();
    }
}

// ---------------- 6a) per-token endpoint scores ----------------------------
__global__ void score_vec_kernel(const float* __restrict__ h1,
                                 const float* __restrict__ mlpw,
                                 float* __restrict__ si, float* __restrict__ sj,
                                 int n) {
    int t = blockIdx.x * blockDim.x + threadIdx.x;
    if (t >= n) return;
    const float* x = h1 + (size_t)t * 100;
    float a = 0.0f, b = 0.0f;
#pragma unroll 4
    for (int k = 0; k < 100; k++) {
        float xv = x[k];
        a += xv * __ldg(mlpw + k);
        b += xv * __ldg(mlpw + 100 + k);
    }
    si[t] = a;
    sj[t] = b;
}

// ---------------- 6b) pairwise epilogue ------------------------------------
__global__ void __launch_bounds__(256)
epilogue_kernel(const float* __restrict__ si, const float* __restrict__ sj,
                const float* __restrict__ mb, float* __restrict__ out, int n) {
    int i = blockIdx.y;
    int j4 = blockIdx.x * blockDim.x + threadIdx.x;
    int j0 = j4 * 4;
    if (j0 >= n) return;
    float base = si[i] + mb[0];
    float4 r;
    r.x = (j0 + 0 > i) ? tanh_acc(base + sj[j0 + 0]) : 0.0f;
    r.y = (j0 + 1 > i) ? tanh_acc(base + sj[j0 + 1]) : 0.0f;
    r.z = (j0 + 2 > i) ? tanh_acc(base + sj[j0 + 2]) : 0.0f;
    r.w = (j0 + 3 > i) ? tanh_acc(base + sj[j0 + 3]) : 0.0f;
    *reinterpret_cast<float4*>(out + (size_t)i * n + j0) = r;
}

// ---------------------------------------------------------------------------
extern "C" void kernel_launch(void* const* d_in, const int* in_sizes, int n_in,
                              void* d_out, int out_size) {
    const int*   tok   = (const int*)d_in[0];
    const float* pos   = (const float*)d_in[1];
    const float* emb   = (const float*)d_in[2];
    const float* wih0f = (const float*)d_in[3];
    const float* whh0f = (const float*)d_in[4];
    const float* b0f   = (const float*)d_in[5];
    const float* wih0b = (const float*)d_in[6];
    const float* whh0b = (const float*)d_in[7];
    const float* b0b   = (const float*)d_in[8];
    const float* wih1f = (const float*)d_in[9];
    const float* whh1f = (const float*)d_in[10];
    const float* b1f   = (const float*)d_in[11];
    const float* wih1b = (const float*)d_in[12];
    const float* whh1b = (const float*)d_in[13];
    const float* b1b   = (const float*)d_in[14];
    const float* mlpw  = (const float*)d_in[15];
    const float* mlpb  = (const float*)d_in[16];

    int n = in_sizes[0];
    if (n > NMAX) n = NMAX;

    float *x0, *pre0, *pre1, *h0, *h1, *si, *sj;
    cudaGetSymbolAddress((void**)&x0,   g_x0);
    cudaGetSymbolAddress((void**)&pre0, g_pre0);
    cudaGetSymbolAddress((void**)&pre1, g_pre1);
    cudaGetSymbolAddress((void**)&h0,   g_h0);
    cudaGetSymbolAddress((void**)&h1,   g_h1);
    cudaGetSymbolAddress((void**)&si,   g_si);
    cudaGetSymbolAddress((void**)&sj,   g_sj);

    build_x0_kernel<<<n, 128>>>(tok, pos, emb, x0, n);

    {
        dim3 grid((n + 63) / 64, (200 + 63) / 64);
        gemm_bias_kernel<<<grid, 256>>>(x0, 352, wih0f, 350, b0f,
                                        pre0, 200, n, 200, 350);
        gemm_bias_kernel<<<grid, 256>>>(x0, 352, wih0b, 350, b0b,
                                        pre0 + (size_t)n * 200, 200, n, 200, 350);
    }

    lstm_layer_kernel<<<2, 128>>>(pre0, whh0f, whh0b, h0, n);

    {
        dim3 grid((n + 63) / 64, (200 + 63) / 64);
        gemm_bias_kernel<<<grid, 256>>>(h0, 100, wih1f, 100, b1f,
                                        pre1, 200, n, 200, 100);
        gemm_bias_kernel<<<grid, 256>>>(h0, 100, wih1b, 100, b1b,
                                        pre1 + (size_t)n * 200, 200, n, 200, 100);
    }

    lstm_layer_kernel<<<2, 128>>>(pre1, whh1f, whh1b, h1, n);

    score_vec_kernel<<<(n + 255) / 256, 256>>>(h1, mlpw, si, sj, n);
    {
        dim3 grid((n / 4 + 255) / 256, n);
        epilogue_kernel<<<grid, 256>>>(si, sj, mlpb, (float*)d_out, n);
    }
}

// round 4
// speedup vs baseline: 1.4431x; 1.3655x over previous
#include <cuda_runtime.h>
#include <cuda_bf16.h>
#include <cstdint>

// ---------------------------------------------------------------------------
// DependencyParsingNetwork: emb-gather + 2-layer BiLSTM (H=50) + pairwise tanh
// R3: branch-free recurrence loop (no BSSY), 4-chain dots, activation scales
// folded into weights (GEMM prescales gate pre-activations by -log2e / -2log2e).
// ---------------------------------------------------------------------------

#define NMAX 8192
#define HH   50
#define L2E  1.4426950408889634f

typedef unsigned long long ull;

__device__ float g_x0[NMAX * 352];          // also reused as garbage dump
__device__ float g_pre0[2 * NMAX * 200];
__device__ float g_pre1[2 * NMAX * 200];
__device__ float g_h0[NMAX * 100];
__device__ float g_h1[NMAX * 100];
__device__ float g_si[NMAX];
__device__ float g_sj[NMAX];

// ---------------- packed f32x2 / MUFU helpers ------------------------------
__device__ __forceinline__ ull pack2(float x, float y) {
    ull r; asm("mov.b64 %0,{%1,%2};" : "=l"(r) : "f"(x), "f"(y)); return r;
}
__device__ __forceinline__ float2 unpack2(ull v) {
    float2 r; asm("mov.b64 {%0,%1},%2;" : "=f"(r.x), "=f"(r.y) : "l"(v)); return r;
}
__device__ __forceinline__ ull fma2(ull a, ull b, ull c) {
    ull d; asm("fma.rn.f32x2 %0,%1,%2,%3;" : "=l"(d) : "l"(a), "l"(b), "l"(c)); return d;
}
__device__ __forceinline__ ull add2(ull a, ull b) {
    ull d; asm("add.rn.f32x2 %0,%1,%2;" : "=l"(d) : "l"(a), "l"(b)); return d;
}
__device__ __forceinline__ float ex2f(float x) {
    float y; asm("ex2.approx.ftz.f32 %0,%1;" : "=f"(y) : "f"(x)); return y;
}
__device__ __forceinline__ float rcpf(float x) {
    float y; asm("rcp.approx.ftz.f32 %0,%1;" : "=f"(y) : "f"(x)); return y;
}
__device__ __forceinline__ float tanh_acc(float x) {
    float e = ex2f(x * (-2.0f * L2E));
    return fmaf(2.0f, rcpf(1.0f + e), -1.0f);
}

// ---------------- 1) build x0 ----------------------------------------------
__global__ void build_x0_kernel(const int* __restrict__ tok,
                                const float* __restrict__ pos,
                                const float* __restrict__ emb,
                                float* __restrict__ x0, int n) {
    int t = blockIdx.x;
    int tk = tok[t];
    for (int k = threadIdx.x; k < 352; k += blockDim.x) {
        float v;
        if (k < 300)      v = emb[(size_t)tk * 300 + k];
        else if (k < 350) v = pos[t * 50 + (k - 300)];
        else              v = 0.0f;
        x0[(size_t)t * 352 + k] = v;
    }
}

// ---------------- 2) GEMM: C = A*B^T + bias, optional gate prescale --------
__global__ void __launch_bounds__(256)
gemm_bias_kernel(const float* __restrict__ A, int lda,
                 const float* __restrict__ B, int ldb,
                 const float* __restrict__ bias,
                 float* __restrict__ C, int ldc,
                 int M, int N, int K, int prescale) {
    const int BM = 64, BN = 64, BK = 16;
    __shared__ __align__(16) float As[BK][BM + 4];
    __shared__ __align__(16) float Bs[BK][BN + 4];
    int tid = threadIdx.x;
    int bm = blockIdx.x * BM, bn = blockIdx.y * BN;
    int tx = tid & 15, ty = tid >> 4;

    float acc[4][4];
#pragma unroll
    for (int i = 0; i < 4; i++)
#pragma unroll
        for (int j = 0; j < 4; j++) acc[i][j] = 0.0f;

    for (int k0 = 0; k0 < K; k0 += BK) {
#pragma unroll
        for (int i = 0; i < 4; i++) {
            int idx = tid + i * 256;
            int kk = idx & 15, m = idx >> 4;
            int gm = bm + m, gk = k0 + kk;
            float v = 0.0f;
            if (gm < M && gk < K) v = A[(size_t)gm * lda + gk];
            As[kk][m] = v;
        }
#pragma unroll
        for (int i = 0; i < 4; i++) {
            int idx = tid + i * 256;
            int kk = idx & 15, nn = idx >> 4;
            int gn = bn + nn, gk = k0 + kk;
            float v = 0.0f;
            if (gn < N && gk < K) v = B[(size_t)gn * ldb + gk];
            Bs[kk][nn] = v;
        }
        __syncthreads();
#pragma unroll
        for (int kk = 0; kk < BK; kk++) {
            float4 a4 = *reinterpret_cast<const float4*>(&As[kk][ty * 4]);
            float4 b4 = *reinterpret_cast<const float4*>(&Bs[kk][tx * 4]);
            float a[4] = {a4.x, a4.y, a4.z, a4.w};
            float b[4] = {b4.x, b4.y, b4.z, b4.w};
#pragma unroll
            for (int i = 0; i < 4; i++)
#pragma unroll
                for (int j = 0; j < 4; j++) acc[i][j] += a[i] * b[j];
        }
        __syncthreads();
    }
#pragma unroll
    for (int i = 0; i < 4; i++) {
        int gm = bm + ty * 4 + i;
        if (gm >= M) continue;
#pragma unroll
        for (int j = 0; j < 4; j++) {
            int gn = bn + tx * 4 + j;
            if (gn < N) {
                float sc = 1.0f;
                if (prescale) sc = (gn >= 100 && gn < 150) ? (-2.0f * L2E) : (-L2E);
                C[(size_t)gm * ldc + gn] = (acc[i][j] + bias[gn]) * sc;
            }
        }
    }
}

// ---------------- 3/5) recurrence: branch-free loop body -------------------
// thread t: j=t>>1, p=t&1. p0 owns gate rows i(j), g(100+j); p1 owns f(50+j),
// o(150+j). Pre-activations arrive already scaled by -log2e (-2log2e for g),
// so sigmoid = rcp(1+ex2(v)), tanh = 2*rcp(1+ex2(v))-1. One xor-1 shfl pair
// delivers (f,o) [resp (i,g)] to the partner; all lanes compute c,h (p1's is
// garbage) and store unconditionally to precomputed real-or-scratch targets.
__global__ void __launch_bounds__(128, 1)
lstm_layer_kernel(const float* __restrict__ pre,   // [2][n][200], prescaled
                  const float* __restrict__ whh_f, // [200][50]
                  const float* __restrict__ whh_b,
                  float* __restrict__ hout,        // [n][100]
                  float* __restrict__ dump,        // garbage sink
                  int n) {
    const int dir = blockIdx.x;
    const float* __restrict__ preD = pre + (size_t)dir * n * 200;
    const float* __restrict__ whh = dir ? whh_b : whh_f;

    const int t = threadIdx.x;
    const int j = t >> 1, p = t & 1;
    const bool wr = (p == 0) && (j < HH);
    const int rA = min(p * HH + j, 199);
    const int rBc = min(p * HH + j + 100, 199);

    const float sclA = -L2E;
    const float sclB = (p == 0) ? (-2.0f * L2E) : (-L2E);
    const float m2  = (p == 0) ? 2.0f : 1.0f;
    const float off = (p == 0) ? -1.0f : 0.0f;

    // persistent prescaled weight rows: 2 x 25 packed pairs
    ull wA[25], wB[25];
#pragma unroll
    for (int k = 0; k < 25; k++) {
        wA[k] = pack2(whh[rA * HH + 2 * k] * sclA, whh[rA * HH + 2 * k + 1] * sclA);
        wB[k] = pack2(whh[rBc * HH + 2 * k] * sclB, whh[rBc * HH + 2 * k + 1] * sclB);
    }

    __shared__ __align__(16) float hsh[2][128];   // [0..49] real, [64..127] scratch
    if (t < 64) { hsh[0][t] = 0.0f; hsh[1][t] = 0.0f; }
    float c = 0.0f;

    // store targets (precomputed; loop body has NO branches)
    float* st0 = &hsh[1][wr ? j : (64 + j)];      // written after reading buf 0
    float* st1 = &hsh[0][wr ? j : (64 + j)];      // written after reading buf 1
    float* phW;
    long long hOffW;
    if (wr) {
        phW = hout + (size_t)(dir ? (n - 1) : 0) * 100 + dir * HH + j;
        hOffW = dir ? -100 : 100;
    } else {
        phW = dump + dir * 256 + t;
        hOffW = 0;
    }

    // 3-deep prefetch with clamped indices
    float a0, b0, a1, b1, a2, b2;
    {
        int s0 = 0, s1 = min(1, n - 1), s2 = min(2, n - 1);
        int t0 = dir ? (n - 1 - s0) : s0;
        int t1 = dir ? (n - 1 - s1) : s1;
        int t2 = dir ? (n - 1 - s2) : s2;
        a0 = preD[(size_t)t0 * 200 + rA]; b0 = preD[(size_t)t0 * 200 + rBc];
        a1 = preD[(size_t)t1 * 200 + rA]; b1 = preD[(size_t)t1 * 200 + rBc];
        a2 = preD[(size_t)t2 * 200 + rA]; b2 = preD[(size_t)t2 * 200 + rBc];
    }
    __syncthreads();

    auto step_fn = [&](const float* hb, float* sts, float pa, float pb) {
        ull hp[25];
#pragma unroll
        for (int i2 = 0; i2 < 12; i2++) {
            ulonglong2 hv = *reinterpret_cast<const ulonglong2*>(hb + 4 * i2);
            hp[2 * i2] = hv.x; hp[2 * i2 + 1] = hv.y;
        }
        hp[24] = *reinterpret_cast<const ull*>(hb + 48);

        ull aA[4], aB[4];
        aA[0] = pack2(pa, 0.0f); aB[0] = pack2(pb, 0.0f);
        aA[1] = pack2(0.0f, 0.0f); aA[2] = aA[1]; aA[3] = aA[1];
        aB[1] = aA[1]; aB[2] = aA[1]; aB[3] = aA[1];
#pragma unroll
        for (int k = 0; k < 25; k++) {
            aA[k & 3] = fma2(wA[k], hp[k], aA[k & 3]);
            aB[k & 3] = fma2(wB[k], hp[k], aB[k & 3]);
        }
        ull sAx = add2(add2(aA[0], aA[1]), add2(aA[2], aA[3]));
        ull sBx = add2(add2(aB[0], aB[1]), add2(aB[2], aB[3]));
        float2 fA = unpack2(sAx), fB = unpack2(sBx);
        float vA = fA.x + fA.y;
        float vB = fB.x + fB.y;

        float yA = rcpf(1.0f + ex2f(vA));                 // sig(i) / sig(f)
        float yB = fmaf(m2, rcpf(1.0f + ex2f(vB)), off);  // tanh(g) / sig(o)
        float mg = yA * yB;                               // i*g (p0)
        float ffx = __shfl_xor_sync(0xFFFFFFFFu, yA, 1);  // sig(f) on p0
        float oox = __shfl_xor_sync(0xFFFFFFFFu, yB, 1);  // sig(o) on p0
        c = fmaf(ffx, c, mg);
        float h = oox * tanh_acc(c);
        *sts = h;
        *phW = h;
        phW += hOffW;
    };

    auto advance = [&](int sload) {
        int ss = min(sload, n - 1);
        int tl = dir ? (n - 1 - ss) : ss;
        const float* pp = preD + (size_t)tl * 200;
        a2 = pp[rA]; b2 = pp[rBc];
    };

    int s = 0;
#pragma unroll 1
    for (; s + 2 <= n; s += 2) {
        float pa = a0, pb = b0;
        a0 = a1; b0 = b1; float na = a2, nb = b2;
        advance(s + 3);
        step_fn(hsh[0], st0, pa, pb);
        __syncthreads();

        pa = na; pb = nb;                 // step s+1 operands were in (a1 slot)
        // after shift: a0 holds s+1? Keep explicit: operands for s+1 are a0,b0
        pa = a0; pb = b0;
        a0 = na; b0 = nb;                 // a0 <- s+2
        a1 = a2; b1 = b2;                 // a1 <- s+3
        advance(s + 4);
        step_fn(hsh[1], st1, pa, pb);
        __syncthreads();
    }
    if (s < n) {
        step_fn(hsh[0], st0, a0, b0);
        __syncthreads();
    }
}

// ---------------- 6a) per-token endpoint scores ----------------------------
__global__ void score_vec_kernel(const float* __restrict__ h1,
                                 const float* __restrict__ mlpw,
                                 float* __restrict__ si, float* __restrict__ sj,
                                 int n) {
    int t = blockIdx.x * blockDim.x + threadIdx.x;
    if (t >= n) return;
    const float* x = h1 + (size_t)t * 100;
    float a = 0.0f, b = 0.0f;
#pragma unroll 4
    for (int k = 0; k < 100; k++) {
        float xv = x[k];
        a += xv * __ldg(mlpw + k);
        b += xv * __ldg(mlpw + 100 + k);
    }
    si[t] = a;
    sj[t] = b;
}

// ---------------- 6b) pairwise epilogue ------------------------------------
__global__ void __launch_bounds__(256)
epilogue_kernel(const float* __restrict__ si, const float* __restrict__ sj,
                const float* __restrict__ mb, float* __restrict__ out, int n) {
    int i = blockIdx.y;
    int j4 = blockIdx.x * blockDim.x + threadIdx.x;
    int j0 = j4 * 4;
    if (j0 >= n) return;
    float base = si[i] + mb[0];
    float4 r;
    r.x = (j0 + 0 > i) ? tanh_acc(base + sj[j0 + 0]) : 0.0f;
    r.y = (j0 + 1 > i) ? tanh_acc(base + sj[j0 + 1]) : 0.0f;
    r.z = (j0 + 2 > i) ? tanh_acc(base + sj[j0 + 2]) : 0.0f;
    r.w = (j0 + 3 > i) ? tanh_acc(base + sj[j0 + 3]) : 0.0f;
    *reinterpret_cast<float4*>(out + (size_t)i * n + j0) = r;
}

// ---------------------------------------------------------------------------
extern "C" void kernel_launch(void* const* d_in, const int* in_sizes, int n_in,
                              void* d_out, int out_size) {
    const int*   tok   = (const int*)d_in[0];
    const float* pos   = (const float*)d_in[1];
    const float* emb   = (const float*)d_in[2];
    const float* wih0f = (const float*)d_in[3];
    const float* whh0f = (const float*)d_in[4];
    const float* b0f   = (const float*)d_in[5];
    const float* wih0b = (const float*)d_in[6];
    const float* whh0b = (const float*)d_in[7];
    const float* b0b   = (const float*)d_in[8];
    const float* wih1f = (const float*)d_in[9];
    const float* whh1f = (const float*)d_in[10];
    const float* b1f   = (const float*)d_in[11];
    const float* wih1b = (const float*)d_in[12];
    const float* whh1b = (const float*)d_in[13];
    const float* b1b   = (const float*)d_in[14];
    const float* mlpw  = (const float*)d_in[15];
    const float* mlpb  = (const float*)d_in[16];

    int n = in_sizes[0];
    if (n > NMAX) n = NMAX;

    float *x0, *pre0, *pre1, *h0, *h1, *si, *sj;
    cudaGetSymbolAddress((void**)&x0,   g_x0);
    cudaGetSymbolAddress((void**)&pre0, g_pre0);
    cudaGetSymbolAddress((void**)&pre1, g_pre1);
    cudaGetSymbolAddress((void**)&h0,   g_h0);
    cudaGetSymbolAddress((void**)&h1,   g_h1);
    cudaGetSymbolAddress((void**)&si,   g_si);
    cudaGetSymbolAddress((void**)&sj,   g_sj);

    build_x0_kernel<<<n, 128>>>(tok, pos, emb, x0, n);

    {
        dim3 grid((n + 63) / 64, (200 + 63) / 64);
        gemm_bias_kernel<<<grid, 256>>>(x0, 352, wih0f, 350, b0f,
                                        pre0, 200, n, 200, 350, 1);
        gemm_bias_kernel<<<grid, 256>>>(x0, 352, wih0b, 350, b0b,
                                        pre0 + (size_t)n * 200, 200, n, 200, 350, 1);
    }

    lstm_layer_kernel<<<2, 128>>>(pre0, whh0f, whh0b, h0, x0, n);

    {
        dim3 grid((n + 63) / 64, (200 + 63) / 64);
        gemm_bias_kernel<<<grid, 256>>>(h0, 100, wih1f, 100, b1f,
                                        pre1, 200, n, 200, 100, 1);
        gemm_bias_kernel<<<grid, 256>>>(h0, 100, wih1b, 100, b1b,
                                        pre1 + (size_t)n * 200, 200, n, 200, 100, 1);
    }

    lstm_layer_kernel<<<2, 128>>>(pre1, whh1f, whh1b, h1, x0, n);

    score_vec_kernel<<<(n + 255) / 256, 256>>>(h1, mlpw, si, sj, n);
    {
        dim3 grid((n / 4 + 255) / 256, n);
        epilogue_kernel<<<grid, 256>>>(si, sj, mlpb, (float*)d_out, n);
    }
}

// round 5
// speedup vs baseline: 1.5167x; 1.0510x over previous
#include <cuda_runtime.h>
#include <cuda_bf16.h>
#include <cstdint>

// ---------------------------------------------------------------------------
// DependencyParsingNetwork: emb-gather + 2-layer BiLSTM (H=50) + pairwise tanh
// R5: HW tanh (MUFU.TANH) for all activations; sigmoid = 0.5*tanh(v/2)+0.5
// with the 0.5 pre-scale folded into GEMM outputs and W_hh register copies.
// Single-shfl gate handoff (p0 -> p1 ships i*g; p1 owns c and writes h).
// ---------------------------------------------------------------------------

#define NMAX 8192
#define HH   50

typedef unsigned long long ull;

__device__ float g_x0[NMAX * 352];          // also reused as garbage dump
__device__ float g_pre0[2 * NMAX * 200];
__device__ float g_pre1[2 * NMAX * 200];
__device__ float g_h0[NMAX * 100];
__device__ float g_h1[NMAX * 100];
__device__ float g_si[NMAX];
__device__ float g_sj[NMAX];

// ---------------- packed f32x2 / MUFU helpers ------------------------------
__device__ __forceinline__ ull pack2(float x, float y) {
    ull r; asm("mov.b64 %0,{%1,%2};" : "=l"(r) : "f"(x), "f"(y)); return r;
}
__device__ __forceinline__ float2 unpack2(ull v) {
    float2 r; asm("mov.b64 {%0,%1},%2;" : "=f"(r.x), "=f"(r.y) : "l"(v)); return r;
}
__device__ __forceinline__ ull fma2(ull a, ull b, ull c) {
    ull d; asm("fma.rn.f32x2 %0,%1,%2,%3;" : "=l"(d) : "l"(a), "l"(b), "l"(c)); return d;
}
__device__ __forceinline__ ull add2(ull a, ull b) {
    ull d; asm("add.rn.f32x2 %0,%1,%2;" : "=l"(d) : "l"(a), "l"(b)); return d;
}
__device__ __forceinline__ float tanhf_hw(float x) {
    float y; asm("tanh.approx.f32 %0,%1;" : "=f"(y) : "f"(x)); return y;
}

// ---------------- 1) build x0 ----------------------------------------------
__global__ void build_x0_kernel(const int* __restrict__ tok,
                                const float* __restrict__ pos,
                                const float* __restrict__ emb,
                                float* __restrict__ x0, int n) {
    int t = blockIdx.x;
    int tk = tok[t];
    for (int k = threadIdx.x; k < 352; k += blockDim.x) {
        float v;
        if (k < 300)      v = emb[(size_t)tk * 300 + k];
        else if (k < 350) v = pos[t * 50 + (k - 300)];
        else              v = 0.0f;
        x0[(size_t)t * 352 + k] = v;
    }
}

// ---------------- 2) GEMM: C = A*B^T + bias, optional gate prescale --------
// prescale: sigmoid rows (i,f,o) get *0.5 (for sig(v)=0.5*tanh(v/2)+0.5);
// tanh rows (g: 100..149) stay *1.
__global__ void __launch_bounds__(256)
gemm_bias_kernel(const float* __restrict__ A, int lda,
                 const float* __restrict__ B, int ldb,
                 const float* __restrict__ bias,
                 float* __restrict__ C, int ldc,
                 int M, int N, int K, int prescale) {
    const int BM = 64, BN = 64, BK = 16;
    __shared__ __align__(16) float As[BK][BM + 4];
    __shared__ __align__(16) float Bs[BK][BN + 4];
    int tid = threadIdx.x;
    int bm = blockIdx.x * BM, bn = blockIdx.y * BN;
    int tx = tid & 15, ty = tid >> 4;

    float acc[4][4];
#pragma unroll
    for (int i = 0; i < 4; i++)
#pragma unroll
        for (int j = 0; j < 4; j++) acc[i][j] = 0.0f;

    for (int k0 = 0; k0 < K; k0 += BK) {
#pragma unroll
        for (int i = 0; i < 4; i++) {
            int idx = tid + i * 256;
            int kk = idx & 15, m = idx >> 4;
            int gm = bm + m, gk = k0 + kk;
            float v = 0.0f;
            if (gm < M && gk < K) v = A[(size_t)gm * lda + gk];
            As[kk][m] = v;
        }
#pragma unroll
        for (int i = 0; i < 4; i++) {
            int idx = tid + i * 256;
            int kk = idx & 15, nn = idx >> 4;
            int gn = bn + nn, gk = k0 + kk;
            float v = 0.0f;
            if (gn < N && gk < K) v = B[(size_t)gn * ldb + gk];
            Bs[kk][nn] = v;
        }
        __syncthreads();
#pragma unroll
        for (int kk = 0; kk < BK; kk++) {
            float4 a4 = *reinterpret_cast<const float4*>(&As[kk][ty * 4]);
            float4 b4 = *reinterpret_cast<const float4*>(&Bs[kk][tx * 4]);
            float a[4] = {a4.x, a4.y, a4.z, a4.w};
            float b[4] = {b4.x, b4.y, b4.z, b4.w};
#pragma unroll
            for (int i = 0; i < 4; i++)
#pragma unroll
                for (int j = 0; j < 4; j++) acc[i][j] += a[i] * b[j];
        }
        __syncthreads();
    }
#pragma unroll
    for (int i = 0; i < 4; i++) {
        int gm = bm + ty * 4 + i;
        if (gm >= M) continue;
#pragma unroll
        for (int j = 0; j < 4; j++) {
            int gn = bn + tx * 4 + j;
            if (gn < N) {
                float sc = 1.0f;
                if (prescale) sc = (gn >= 100 && gn < 150) ? 1.0f : 0.5f;
                C[(size_t)gm * ldc + gn] = (acc[i][j] + bias[gn]) * sc;
            }
        }
    }
}

// ---------------- 3/5) recurrence: branch-free, MUFU.TANH activations ------
// thread t: j=t>>1, p=t&1. p0 owns rows i(j), g(100+j); p1 owns f(50+j),
// o(150+j). Pre-acts arrive scaled by 0.5 (sigmoid rows) / 1.0 (g rows).
// gate = fma(m, tanh(u), cst): sigmoid m=0.5,cst=0.5; tanh m=1,cst=0.
// p0 ships mg=i*g via one xor-1 shfl; p1 keeps c, computes h, stores.
__global__ void __launch_bounds__(128, 1)
lstm_layer_kernel(const float* __restrict__ pre,   // [2][n][200], prescaled
                  const float* __restrict__ whh_f, // [200][50]
                  const float* __restrict__ whh_b,
                  float* __restrict__ hout,        // [n][100]
                  float* __restrict__ dump,        // garbage sink
                  int n) {
    const int dir = blockIdx.x;
    const float* __restrict__ preD = pre + (size_t)dir * n * 200;
    const float* __restrict__ whh = dir ? whh_b : whh_f;

    const int t = threadIdx.x;
    const int j = t >> 1, p = t & 1;
    const bool wr = (p == 1) && (j < HH);       // p1 writes h now
    const int rA = min(p * HH + j, 199);        // i (p0) / f (p1)
    const int rBc = min(p * HH + j + 100, 199); // g (p0) / o (p1)

    const float sclA = 0.5f;                         // i,f are sigmoid
    const float sclB = (p == 0) ? 1.0f : 0.5f;       // g tanh / o sigmoid
    const float mB   = (p == 0) ? 1.0f : 0.5f;
    const float cstB = (p == 0) ? 0.0f : 0.5f;

    // persistent prescaled weight rows: 2 x 25 packed pairs
    ull wA[25], wB[25];
#pragma unroll
    for (int k = 0; k < 25; k++) {
        wA[k] = pack2(whh[rA * HH + 2 * k] * sclA, whh[rA * HH + 2 * k + 1] * sclA);
        wB[k] = pack2(whh[rBc * HH + 2 * k] * sclB, whh[rBc * HH + 2 * k + 1] * sclB);
    }

    __shared__ __align__(16) float hsh[2][128];   // [0..49] real, [64..127] scratch
    if (t < 64) { hsh[0][t] = 0.0f; hsh[1][t] = 0.0f; }
    float c = 0.0f;

    // precomputed store targets -> zero branches in the loop body
    float* st0 = &hsh[1][wr ? j : (64 + j)];
    float* st1 = &hsh[0][wr ? j : (64 + j)];
    float* phW;
    long long hOffW;
    if (wr) {
        phW = hout + (size_t)(dir ? (n - 1) : 0) * 100 + dir * HH + j;
        hOffW = dir ? -100 : 100;
    } else {
        phW = dump + dir * 256 + t;
        hOffW = 0;
    }

    // 3-deep prefetch with clamped indices
    float a0, b0, a1, b1, a2, b2;
    {
        int s0 = 0, s1 = min(1, n - 1), s2 = min(2, n - 1);
        int t0 = dir ? (n - 1 - s0) : s0;
        int t1 = dir ? (n - 1 - s1) : s1;
        int t2 = dir ? (n - 1 - s2) : s2;
        a0 = preD[(size_t)t0 * 200 + rA]; b0 = preD[(size_t)t0 * 200 + rBc];
        a1 = preD[(size_t)t1 * 200 + rA]; b1 = preD[(size_t)t1 * 200 + rBc];
        a2 = preD[(size_t)t2 * 200 + rA]; b2 = preD[(size_t)t2 * 200 + rBc];
    }
    __syncthreads();

    auto step_fn = [&](const float* hb, float* sts, float pa, float pb) {
        ull hp[25];
#pragma unroll
        for (int i2 = 0; i2 < 12; i2++) {
            ulonglong2 hv = *reinterpret_cast<const ulonglong2*>(hb + 4 * i2);
            hp[2 * i2] = hv.x; hp[2 * i2 + 1] = hv.y;
        }
        hp[24] = *reinterpret_cast<const ull*>(hb + 48);

        ull aA[4], aB[4];
        aA[0] = pack2(pa, 0.0f); aB[0] = pack2(pb, 0.0f);
        aA[1] = pack2(0.0f, 0.0f); aA[2] = aA[1]; aA[3] = aA[1];
        aB[1] = aA[1]; aB[2] = aA[1]; aB[3] = aA[1];
#pragma unroll
        for (int k = 0; k < 25; k++) {
            aA[k & 3] = fma2(wA[k], hp[k], aA[k & 3]);
            aB[k & 3] = fma2(wB[k], hp[k], aB[k & 3]);
        }
        ull sAx = add2(add2(aA[0], aA[1]), add2(aA[2], aA[3]));
        ull sBx = add2(add2(aB[0], aB[1]), add2(aB[2], aB[3]));
        float2 fA = unpack2(sAx), fB = unpack2(sBx);
        float vA = fA.x + fA.y;
        float vB = fB.x + fB.y;

        // activations: yA = sig (p0:i, p1:f); yB = p0: tanh(g), p1: sig(o)
        float yA = fmaf(0.5f, tanhf_hw(vA), 0.5f);
        float yB = fmaf(mB, tanhf_hw(vB), cstB);

        float mg = yA * yB;                               // i*g on p0
        float mgx = __shfl_xor_sync(0xFFFFFFFFu, mg, 1);  // p1 receives i*g
        c = fmaf(yA, c, mgx);                             // p1: f*c + i*g
        float h = yB * tanhf_hw(c);                       // p1: o * tanh(c)
        *sts = h;
        *phW = h;
        phW += hOffW;
    };

    auto advance = [&](int sload) {
        int ss = min(sload, n - 1);
        int tl = dir ? (n - 1 - ss) : ss;
        const float* pp = preD + (size_t)tl * 200;
        a2 = pp[rA]; b2 = pp[rBc];
    };

    int s = 0;
#pragma unroll 1
    for (; s + 2 <= n; s += 2) {
        float pa = a0, pb = b0;
        float na = a2, nb = b2;
        a0 = a1; b0 = b1;
        advance(s + 3);
        step_fn(hsh[0], st0, pa, pb);
        __syncthreads();

        pa = a0; pb = b0;
        a0 = na; b0 = nb;
        a1 = a2; b1 = b2;
        advance(s + 4);
        step_fn(hsh[1], st1, pa, pb);
        __syncthreads();
    }
    if (s < n) {
        step_fn(hsh[0], st0, a0, b0);
        __syncthreads();
    }
}

// ---------------- 6a) per-token endpoint scores ----------------------------
__global__ void score_vec_kernel(const float* __restrict__ h1,
                                 const float* __restrict__ mlpw,
                                 float* __restrict__ si, float* __restrict__ sj,
                                 int n) {
    int t = blockIdx.x * blockDim.x + threadIdx.x;
    if (t >= n) return;
    const float* x = h1 + (size_t)t * 100;
    float a = 0.0f, b = 0.0f;
#pragma unroll 4
    for (int k = 0; k < 100; k++) {
        float xv = x[k];
        a += xv * __ldg(mlpw + k);
        b += xv * __ldg(mlpw + 100 + k);
    }
    si[t] = a;
    sj[t] = b;
}

// ---------------- 6b) pairwise epilogue ------------------------------------
__global__ void __launch_bounds__(256)
epilogue_kernel(const float* __restrict__ si, const float* __restrict__ sj,
                const float* __restrict__ mb, float* __restrict__ out, int n) {
    int i = blockIdx.y;
    int j4 = blockIdx.x * blockDim.x + threadIdx.x;
    int j0 = j4 * 4;
    if (j0 >= n) return;
    float base = si[i] + mb[0];
    float4 r;
    r.x = (j0 + 0 > i) ? tanhf_hw(base + sj[j0 + 0]) : 0.0f;
    r.y = (j0 + 1 > i) ? tanhf_hw(base + sj[j0 + 1]) : 0.0f;
    r.z = (j0 + 2 > i) ? tanhf_hw(base + sj[j0 + 2]) : 0.0f;
    r.w = (j0 + 3 > i) ? tanhf_hw(base + sj[j0 + 3]) : 0.0f;
    *reinterpret_cast<float4*>(out + (size_t)i * n + j0) = r;
}

// ---------------------------------------------------------------------------
extern "C" void kernel_launch(void* const* d_in, const int* in_sizes, int n_in,
                              void* d_out, int out_size) {
    const int*   tok   = (const int*)d_in[0];
    const float* pos   = (const float*)d_in[1];
    const float* emb   = (const float*)d_in[2];
    const float* wih0f = (const float*)d_in[3];
    const float* whh0f = (const float*)d_in[4];
    const float* b0f   = (const float*)d_in[5];
    const float* wih0b = (const float*)d_in[6];
    const float* whh0b = (const float*)d_in[7];
    const float* b0b   = (const float*)d_in[8];
    const float* wih1f = (const float*)d_in[9];
    const float* whh1f = (const float*)d_in[10];
    const float* b1f   = (const float*)d_in[11];
    const float* wih1b = (const float*)d_in[12];
    const float* whh1b = (const float*)d_in[13];
    const float* b1b   = (const float*)d_in[14];
    const float* mlpw  = (const float*)d_in[15];
    const float* mlpb  = (const float*)d_in[16];

    int n = in_sizes[0];
    if (n > NMAX) n = NMAX;

    float *x0, *pre0, *pre1, *h0, *h1, *si, *sj;
    cudaGetSymbolAddress((void**)&x0,   g_x0);
    cudaGetSymbolAddress((void**)&pre0, g_pre0);
    cudaGetSymbolAddress((void**)&pre1, g_pre1);
    cudaGetSymbolAddress((void**)&h0,   g_h0);
    cudaGetSymbolAddress((void**)&h1,   g_h1);
    cudaGetSymbolAddress((void**)&si,   g_si);
    cudaGetSymbolAddress((void**)&sj,   g_sj);

    build_x0_kernel<<<n, 128>>>(tok, pos, emb, x0, n);

    {
        dim3 grid((n + 63) / 64, (200 + 63) / 64);
        gemm_bias_kernel<<<grid, 256>>>(x0, 352, wih0f, 350, b0f,
                                        pre0, 200, n, 200, 350, 1);
        gemm_bias_kernel<<<grid, 256>>>(x0, 352, wih0b, 350, b0b,
                                        pre0 + (size_t)n * 200, 200, n, 200, 350, 1);
    }

    lstm_layer_kernel<<<2, 128>>>(pre0, whh0f, whh0b, h0, x0, n);

    {
        dim3 grid((n + 63) / 64, (200 + 63) / 64);
        gemm_bias_kernel<<<grid, 256>>>(h0, 100, wih1f, 100, b1f,
                                        pre1, 200, n, 200, 100, 1);
        gemm_bias_kernel<<<grid, 256>>>(h0, 100, wih1b, 100, b1b,
                                        pre1 + (size_t)n * 200, 200, n, 200, 100, 1);
    }

    lstm_layer_kernel<<<2, 128>>>(pre1, whh1f, whh1b, h1, x0, n);

    score_vec_kernel<<<(n + 255) / 256, 256>>>(h1, mlpw, si, sj, n);
    {
        dim3 grid((n / 4 + 255) / 256, n);
        epilogue_kernel<<<grid, 256>>>(si, sj, mlpb, (float*)d_out, n);
    }
}